// round 10
// baseline (speedup 1.0000x reference)
#include <cuda_runtime.h>
#include <cuda_fp16.h>
#include <cuda_bf16.h>

// Channels-last fp16 scratch: per level [B][H*W][256]. Bases in elements.
#define FB0 0
#define FB1 16777216            // + 4*128*128*256
#define FB2 20971520            // + 4*64*64*256
#define FB3 22020096            // + 4*32*32*256
#define FB4 22282240            // + 4*16*16*256
#define FT_TOTAL 22347776       // + 4*8*8*256

__device__ __half g_fth[FT_TOTAL];   // ~44.7 MB — resident in L2

// half2 -> packed f32x2 (2 CVT)
__device__ __forceinline__ float2 h2f2(__half2 h) {
    float2 f;
    unsigned int u = *(unsigned int*)&h;
    asm("{.reg .b16 a, b;\n\t"
        "mov.b32 {a, b}, %2;\n\t"
        "cvt.f32.f16 %0, a;\n\t"
        "cvt.f32.f16 %1, b;}\n\t" : "=f"(f.x), "=f"(f.y) : "r"(u));
    return f;
}

// ---------------- merged transpose: [b][c][s] -> [b][s][c] fp16, 32ch x 128s tiles ----------------
__global__ __launch_bounds__(256) void transpose_all(
    const float* __restrict__ f0, const float* __restrict__ f1,
    const float* __restrict__ f2, const float* __restrict__ f3,
    const float* __restrict__ f4)
{
    __shared__ float tile[32 * 129];    // pitch 129: conflict-free both phases
    int bid = blockIdx.x;
    const float* in; int HH, base, ntile;
    if (bid < 4096)      { in = f0; HH = 16384; base = FB0; ntile = 128; }
    else if (bid < 5120) { in = f1; HH = 4096;  base = FB1; ntile = 32; bid -= 4096; }
    else if (bid < 5376) { in = f2; HH = 1024;  base = FB2; ntile = 8;  bid -= 5120; }
    else if (bid < 5440) { in = f3; HH = 256;   base = FB3; ntile = 2;  bid -= 5376; }
    else                 { in = f4; HH = 64;    base = FB4; ntile = 1;  bid -= 5440; }

    const int st = bid % ntile;                 // spatial tile (128 wide)
    const int r  = bid / ntile;
    const int ct = r & 7;                       // channel tile (8 x 32ch)
    const int b  = r >> 3;                      // batch
    const int tid = threadIdx.x;
    const int s_base = st * 128;

    // Load phase: thread (lc = ch, q): 4 float4 loads.
    const int lc = tid >> 3;
    const int q  = tid & 7;
    const float* ip = in + (long)(b * 256 + ct * 32 + lc) * HH + s_base;
    #pragma unroll
    for (int j = 0; j < 4; j++) {
        const int s = q * 4 + j * 32;
        if (s_base + s < HH) {
            const float4 v = *(const float4*)(ip + s);
            float* tp = tile + lc * 129 + s;
            tp[0] = v.x; tp[1] = v.y; tp[2] = v.z; tp[3] = v.w;
        }
    }
    __syncthreads();

    // Store phase: thread (s, 16-ch half): pack 16 ch -> 2 uint4 stores.
    const int s_l  = tid >> 1;
    const int half = tid & 1;
    if (s_base + s_l < HH) {
        const int c16 = half * 16;
        __half2 hs[8];
        #pragma unroll
        for (int i = 0; i < 8; i++)
            hs[i] = __floats2half2_rn(tile[(c16 + 2*i) * 129 + s_l],
                                      tile[(c16 + 2*i + 1) * 129 + s_l]);
        __half* dst = g_fth + base + ((long)b * HH + s_base + s_l) * 256 + ct * 32 + c16;
        *(uint4*)(dst)     = ((const uint4*)hs)[0];
        *(uint4*)(dst + 8) = ((const uint4*)hs)[1];
    }
}

// ---------------- main kernel: block = (ROI, 128-ch tile), fp16 chained accumulation ----------------
#define SB_PITCH 132
__global__ __launch_bounds__(256) void msroi8(
    const float* __restrict__ rois, float* __restrict__ out)
{
    __shared__ int   sxo0[14], sxo1[14], syo0[14], syo1[14];
    __shared__ float swx0[14], swx1[14], swy0[14], swy1[14];
    __shared__ float sbuf[49 * SB_PITCH];           // one 128-ch output tile

    const int roi = blockIdx.x >> 1;                // b*256 + n
    const int ct  = blockIdx.x & 1;                 // channel tile
    const int b   = roi >> 8;
    const int tid = threadIdx.x;

    if (tid < 28) {
        const float rx1 = rois[roi*4+0], ry1 = rois[roi*4+1];
        const float rx2 = rois[roi*4+2], ry2 = rois[roi*4+3];
        const float area = (rx2 - rx1) * (ry2 - ry1);
        float lv = floorf(4.0f + log2f(sqrtf(area) / 224.0f + 1e-6f));
        lv = fminf(fmaxf(lv, 2.0f), 6.0f);
        const int lvl = (int)lv - 2;

        int H, base; float scale;
        switch (lvl) {
            case 0:  H = 128; base = FB0; scale = 0.25f;     break;
            case 1:  H = 64;  base = FB1; scale = 0.125f;    break;
            case 2:  H = 32;  base = FB2; scale = 0.0625f;   break;
            case 3:  H = 16;  base = FB3; scale = 0.03125f;  break;
            default: H = 8;   base = FB4; scale = 0.015625f; break;
        }
        const float x1 = rx1 * scale, y1 = ry1 * scale;
        const float bw = fmaxf(rx2 * scale - x1, 1.0f) / 7.0f;
        const float bh = fmaxf(ry2 * scale - y1, 1.0f) / 7.0f;

        const bool isY = tid >= 14;
        const int  i   = isY ? tid - 14 : tid;
        const float g = 0.25f + 0.5f * (float)i;              // == k + (sr+0.5)/2
        const float p = isY ? (y1 + g * bh) : (x1 + g * bw);
        const float v = (p >= -1.0f && p <= (float)H) ? 0.5f : 0.0f;  // validity * sqrt(2x2 mean)
        const float pc = fminf(fmaxf(p, 0.0f), (float)(H - 1));
        const float pf = floorf(pc);
        const float l  = pc - pf;
        const int p0 = (int)pf;
        const int p1 = min(p0 + 1, H - 1);
        if (isY) {
            syo0[i] = base + ((b * H + p0) * H) * 256;
            syo1[i] = base + ((b * H + p1) * H) * 256;
            swy0[i] = (1.0f - l) * v;  swy1[i] = l * v;
        } else {
            sxo0[i] = p0 * 256;  sxo1[i] = p1 * 256;
            swx0[i] = (1.0f - l) * v;  swx1[i] = l * v;
        }
    }
    __syncthreads();

    const int c8   = (tid & 15) * 8;   // 8-channel oct within the 128-ch tile
    const int bg   = tid >> 4;         // 16 bin groups
    const int cofs = ct * 128 + c8;

    for (int bin = bg; bin < 49; bin += 16) {
        const int oy = bin / 7;
        const int ox = bin - oy * 7;
        const __half2 hz = __float2half2_rn(0.0f);
        __half2 acc0 = hz, acc1 = hz, acc2 = hz, acc3 = hz;
        #pragma unroll
        for (int sy = 0; sy < 2; sy++) {
            const int gy = 2 * oy + sy;
            const __half* __restrict__ r0 = g_fth + syo0[gy] + cofs;
            const __half* __restrict__ r1 = g_fth + syo1[gy] + cofs;
            const float wy0 = swy0[gy], wy1 = swy1[gy];
            #pragma unroll
            for (int sx = 0; sx < 2; sx++) {
                const int gx  = 2 * ox + sx;
                const int xo0 = sxo0[gx], xo1 = sxo1[gx];
                const __half2 W00 = __float2half2_rn(wy0 * swx0[gx]);
                const __half2 W01 = __float2half2_rn(wy0 * swx1[gx]);
                const __half2 W10 = __float2half2_rn(wy1 * swx0[gx]);
                const __half2 W11 = __float2half2_rn(wy1 * swx1[gx]);
                const uint4 q00 = *(const uint4*)(r0 + xo0);
                const uint4 q01 = *(const uint4*)(r0 + xo1);
                const uint4 q10 = *(const uint4*)(r1 + xo0);
                const uint4 q11 = *(const uint4*)(r1 + xo1);
                #pragma unroll
                for (int k = 0; k < 4; k++) {
                    const __half2 h00 = ((const __half2*)&q00)[k];
                    const __half2 h01 = ((const __half2*)&q01)[k];
                    const __half2 h10 = ((const __half2*)&q10)[k];
                    const __half2 h11 = ((const __half2*)&q11)[k];
                    __half2 a = (k == 0) ? acc0 : (k == 1) ? acc1 : (k == 2) ? acc2 : acc3;
                    a = __hfma2(h00, W00,
                        __hfma2(h01, W01,
                        __hfma2(h10, W10,
                        __hfma2(h11, W11, a))));
                    if (k == 0) acc0 = a; else if (k == 1) acc1 = a;
                    else if (k == 2) acc2 = a; else acc3 = a;
                }
            }
        }
        const float2 p0 = h2f2(acc0);
        const float2 p1 = h2f2(acc1);
        const float2 p2 = h2f2(acc2);
        const float2 p3 = h2f2(acc3);
        float* sp = sbuf + bin * SB_PITCH + c8;
        *(float4*)(sp    ) = make_float4(p0.x, p0.y, p1.x, p1.y);
        *(float4*)(sp + 4) = make_float4(p2.x, p2.y, p3.x, p3.y);
    }
    __syncthreads();

    // Conflict-free flush: LDS.128 along channels (lane = bin), coalesced STG.32.
    // bank-quad start = 4*b2 -> each 8-lane phase covers 8 distinct quads.
    float* __restrict__ op = out + (long)roi * 12544 + ct * 6272;
    const int warp = tid >> 5, lane = tid & 31;
    #pragma unroll
    for (int j = 0; j < 4; j++) {
        const int c4 = (warp * 4 + j) * 4;          // channel quad 0..124
        #pragma unroll
        for (int rnd = 0; rnd < 2; rnd++) {
            const int b2 = lane + rnd * 32;
            if (b2 < 49) {
                const float4 v = *(const float4*)(sbuf + b2 * SB_PITCH + c4);
                op[(c4 + 0) * 49 + b2] = v.x;
                op[(c4 + 1) * 49 + b2] = v.y;
                op[(c4 + 2) * 49 + b2] = v.z;
                op[(c4 + 3) * 49 + b2] = v.w;
            }
        }
    }
}

extern "C" void kernel_launch(void* const* d_in, const int* in_sizes, int n_in,
                              void* d_out, int out_size) {
    const float* f0   = (const float*)d_in[0];
    const float* f1   = (const float*)d_in[1];
    const float* f2   = (const float*)d_in[2];
    const float* f3   = (const float*)d_in[3];
    const float* f4   = (const float*)d_in[4];
    const float* rois = (const float*)d_in[5];
    float* out        = (float*)d_out;

    transpose_all<<<5472, 256>>>(f0, f1, f2, f3, f4);
    msroi8<<<2048, 256>>>(rois, out);
}

// round 11
// speedup vs baseline: 1.4285x; 1.4285x over previous
#include <cuda_runtime.h>
#include <cuda_fp16.h>
#include <cuda_bf16.h>

// Channels-last fp16 scratch: per level [B][H*W][256]. Bases in elements.
#define FB0 0
#define FB1 16777216            // + 4*128*128*256
#define FB2 20971520            // + 4*64*64*256
#define FB3 22020096            // + 4*32*32*256
#define FB4 22282240            // + 4*16*16*256
#define FT_TOTAL 22347776       // + 4*8*8*256

__device__ __half g_fth[FT_TOTAL];   // ~44.7 MB — resident in L2

// half2 -> packed f32x2 (2 CVT)
__device__ __forceinline__ float2 h2f2(__half2 h) {
    float2 f;
    unsigned int u = *(unsigned int*)&h;
    asm("{.reg .b16 a, b;\n\t"
        "mov.b32 {a, b}, %2;\n\t"
        "cvt.f32.f16 %0, a;\n\t"
        "cvt.f32.f16 %1, b;}\n\t" : "=f"(f.x), "=f"(f.y) : "r"(u));
    return f;
}

// ---------------- merged transpose: [b][c][s] -> [b][s][c] fp16, 32ch x 128s tiles ----------------
__global__ __launch_bounds__(256) void transpose_all(
    const float* __restrict__ f0, const float* __restrict__ f1,
    const float* __restrict__ f2, const float* __restrict__ f3,
    const float* __restrict__ f4)
{
    __shared__ float tile[32 * 129];    // pitch 129: conflict-free both phases
    int bid = blockIdx.x;
    const float* in; int HH, base, ntile;
    if (bid < 4096)      { in = f0; HH = 16384; base = FB0; ntile = 128; }
    else if (bid < 5120) { in = f1; HH = 4096;  base = FB1; ntile = 32; bid -= 4096; }
    else if (bid < 5376) { in = f2; HH = 1024;  base = FB2; ntile = 8;  bid -= 5120; }
    else if (bid < 5440) { in = f3; HH = 256;   base = FB3; ntile = 2;  bid -= 5376; }
    else                 { in = f4; HH = 64;    base = FB4; ntile = 1;  bid -= 5440; }

    const int st = bid % ntile;                 // spatial tile (128 wide)
    const int r  = bid / ntile;
    const int ct = r & 7;                       // channel tile (8 x 32ch)
    const int b  = r >> 3;                      // batch
    const int tid = threadIdx.x;
    const int s_base = st * 128;

    // Load phase: thread (lc = ch, q): 4 float4 loads.
    const int lc = tid >> 3;
    const int q  = tid & 7;
    const float* ip = in + (long)(b * 256 + ct * 32 + lc) * HH + s_base;
    #pragma unroll
    for (int j = 0; j < 4; j++) {
        const int s = q * 4 + j * 32;
        if (s_base + s < HH) {
            const float4 v = *(const float4*)(ip + s);
            float* tp = tile + lc * 129 + s;
            tp[0] = v.x; tp[1] = v.y; tp[2] = v.z; tp[3] = v.w;
        }
    }
    __syncthreads();

    // Store phase: thread (s, 16-ch half): pack 16 ch -> 2 uint4 stores.
    const int s_l  = tid >> 1;
    const int half = tid & 1;
    if (s_base + s_l < HH) {
        const int c16 = half * 16;
        __half2 hs[8];
        #pragma unroll
        for (int i = 0; i < 8; i++)
            hs[i] = __floats2half2_rn(tile[(c16 + 2*i) * 129 + s_l],
                                      tile[(c16 + 2*i + 1) * 129 + s_l]);
        __half* dst = g_fth + base + ((long)b * HH + s_base + s_l) * 256 + ct * 32 + c16;
        *(uint4*)(dst)     = ((const uint4*)hs)[0];
        *(uint4*)(dst + 8) = ((const uint4*)hs)[1];
    }
}

// ---------------- main kernel: block = (ROI, 128-ch tile), static 3+1 bin unroll ----------------
#define SB_PITCH 132
__global__ __launch_bounds__(256) void msroi9(
    const float* __restrict__ rois, float* __restrict__ out)
{
    __shared__ int   sxo0[14], sxo1[14], syo0[14], syo1[14];
    __shared__ float swx0[14], swx1[14], swy0[14], swy1[14];
    __shared__ float sbuf[49 * SB_PITCH];           // one 128-ch output tile

    const int roi = blockIdx.x >> 1;                // b*256 + n
    const int ct  = blockIdx.x & 1;                 // channel tile
    const int b   = roi >> 8;
    const int tid = threadIdx.x;

    if (tid < 28) {
        const float rx1 = rois[roi*4+0], ry1 = rois[roi*4+1];
        const float rx2 = rois[roi*4+2], ry2 = rois[roi*4+3];
        const float area = (rx2 - rx1) * (ry2 - ry1);
        float lv = floorf(4.0f + log2f(sqrtf(area) / 224.0f + 1e-6f));
        lv = fminf(fmaxf(lv, 2.0f), 6.0f);
        const int lvl = (int)lv - 2;

        int H, base; float scale;
        switch (lvl) {
            case 0:  H = 128; base = FB0; scale = 0.25f;     break;
            case 1:  H = 64;  base = FB1; scale = 0.125f;    break;
            case 2:  H = 32;  base = FB2; scale = 0.0625f;   break;
            case 3:  H = 16;  base = FB3; scale = 0.03125f;  break;
            default: H = 8;   base = FB4; scale = 0.015625f; break;
        }
        const float x1 = rx1 * scale, y1 = ry1 * scale;
        const float bw = fmaxf(rx2 * scale - x1, 1.0f) / 7.0f;
        const float bh = fmaxf(ry2 * scale - y1, 1.0f) / 7.0f;

        const bool isY = tid >= 14;
        const int  i   = isY ? tid - 14 : tid;
        const float g = 0.25f + 0.5f * (float)i;              // == k + (sr+0.5)/2
        const float p = isY ? (y1 + g * bh) : (x1 + g * bw);
        const float v = (p >= -1.0f && p <= (float)H) ? 0.5f : 0.0f;  // validity * sqrt(2x2 mean)
        const float pc = fminf(fmaxf(p, 0.0f), (float)(H - 1));
        const float pf = floorf(pc);
        const float l  = pc - pf;
        const int p0 = (int)pf;
        const int p1 = min(p0 + 1, H - 1);
        if (isY) {
            syo0[i] = base + ((b * H + p0) * H) * 256;
            syo1[i] = base + ((b * H + p1) * H) * 256;
            swy0[i] = (1.0f - l) * v;  swy1[i] = l * v;
        } else {
            sxo0[i] = p0 * 256;  sxo1[i] = p1 * 256;
            swx0[i] = (1.0f - l) * v;  swx1[i] = l * v;
        }
    }
    __syncthreads();

    const int c8   = (tid & 15) * 8;   // 8-channel oct within the 128-ch tile
    const int bg   = tid >> 4;         // 16 bin groups
    const int cofs = ct * 128 + c8;

    auto process_bin = [&](int bin) {
        const int oy = bin / 7;
        const int ox = bin - oy * 7;
        const __half2 hz = __float2half2_rn(0.0f);
        __half2 acc0 = hz, acc1 = hz, acc2 = hz, acc3 = hz;
        #pragma unroll
        for (int sy = 0; sy < 2; sy++) {
            const int gy = 2 * oy + sy;
            const __half* __restrict__ r0 = g_fth + syo0[gy] + cofs;
            const __half* __restrict__ r1 = g_fth + syo1[gy] + cofs;
            const float wy0 = swy0[gy], wy1 = swy1[gy];
            #pragma unroll
            for (int sx = 0; sx < 2; sx++) {
                const int gx  = 2 * ox + sx;
                const int xo0 = sxo0[gx], xo1 = sxo1[gx];
                const __half2 W00 = __float2half2_rn(wy0 * swx0[gx]);
                const __half2 W01 = __float2half2_rn(wy0 * swx1[gx]);
                const __half2 W10 = __float2half2_rn(wy1 * swx0[gx]);
                const __half2 W11 = __float2half2_rn(wy1 * swx1[gx]);
                const uint4 q00 = *(const uint4*)(r0 + xo0);
                const uint4 q01 = *(const uint4*)(r0 + xo1);
                const uint4 q10 = *(const uint4*)(r1 + xo0);
                const uint4 q11 = *(const uint4*)(r1 + xo1);
                #pragma unroll
                for (int k = 0; k < 4; k++) {
                    const __half2 h00 = ((const __half2*)&q00)[k];
                    const __half2 h01 = ((const __half2*)&q01)[k];
                    const __half2 h10 = ((const __half2*)&q10)[k];
                    const __half2 h11 = ((const __half2*)&q11)[k];
                    __half2 a = (k == 0) ? acc0 : (k == 1) ? acc1 : (k == 2) ? acc2 : acc3;
                    a = __hfma2(h00, W00,
                        __hfma2(h01, W01,
                        __hfma2(h10, W10,
                        __hfma2(h11, W11, a))));
                    if (k == 0) acc0 = a; else if (k == 1) acc1 = a;
                    else if (k == 2) acc2 = a; else acc3 = a;
                }
            }
        }
        const float2 p0 = h2f2(acc0);
        const float2 p1 = h2f2(acc1);
        const float2 p2 = h2f2(acc2);
        const float2 p3 = h2f2(acc3);
        float* sp = sbuf + bin * SB_PITCH + c8;
        *(float4*)(sp    ) = make_float4(p0.x, p0.y, p1.x, p1.y);
        *(float4*)(sp + 4) = make_float4(p2.x, p2.y, p3.x, p3.y);
    };

    // 49 = 3*16 + 1: three static iterations for all threads (bg+32 <= 47),
    // plus bin 48 handled by the bg==0 group. Static trip counts let ptxas
    // front-batch all three bins' gathers (3x MLP per thread).
    #pragma unroll
    for (int t = 0; t < 3; t++)
        process_bin(bg + t * 16);
    if (bg == 0)
        process_bin(48);
    __syncthreads();

    // Conflict-free flush: LDS.128 along channels (lane = bin), coalesced STG.32.
    float* __restrict__ op = out + (long)roi * 12544 + ct * 6272;
    const int warp = tid >> 5, lane = tid & 31;
    #pragma unroll
    for (int j = 0; j < 4; j++) {
        const int c4 = (warp * 4 + j) * 4;          // channel quad 0..124
        #pragma unroll
        for (int rnd = 0; rnd < 2; rnd++) {
            const int b2 = lane + rnd * 32;
            if (b2 < 49) {
                const float4 v = *(const float4*)(sbuf + b2 * SB_PITCH + c4);
                op[(c4 + 0) * 49 + b2] = v.x;
                op[(c4 + 1) * 49 + b2] = v.y;
                op[(c4 + 2) * 49 + b2] = v.z;
                op[(c4 + 3) * 49 + b2] = v.w;
            }
        }
    }
}

extern "C" void kernel_launch(void* const* d_in, const int* in_sizes, int n_in,
                              void* d_out, int out_size) {
    const float* f0   = (const float*)d_in[0];
    const float* f1   = (const float*)d_in[1];
    const float* f2   = (const float*)d_in[2];
    const float* f3   = (const float*)d_in[3];
    const float* f4   = (const float*)d_in[4];
    const float* rois = (const float*)d_in[5];
    float* out        = (float*)d_out;

    transpose_all<<<5472, 256>>>(f0, f1, f2, f3, f4);
    msroi9<<<2048, 256>>>(rois, out);
}